// round 1
// baseline (speedup 1.0000x reference)
#include <cuda_runtime.h>
#include <math.h>

// ---------------- problem constants ----------------
constexpr int CB = 2;        // batch
constexpr int CS = 2048;     // seq
constexpr int CD = 1024;     // model dim
constexpr int CH = 8;        // heads
constexpr int CHD = 128;     // head dim
constexpr int CM = CB * CS;  // 4096 rows

// ---------------- scratch (device globals; no allocations allowed) ----------
__device__ float g_K[CB * CS * CD];   // key projection  [B,S,D]
__device__ float g_V[CB * CS * CD];   // value projection
__device__ float g_Sf[CB * CS * CD];  // self_force = x @ Wself^T
__device__ float g_P[CB * CS * CD];   // pairwise (attention output)

// ============================================================================
// GEMM: C[m,n] = sum_k A[m,k] * W[n,k]     (i.e. A @ W^T, torch Linear)
// MODE 0: A=arg(x), C=g_K
// MODE 1: A=arg(x), C=g_V
// MODE 2: A=arg(x), C=g_Sf
// MODE 3: A=g_P + g_Sf (fused add), C=arg(out)
// Fixed shape M=4096, N=1024, K=1024. 128x128x32 tiles, 256 threads, 8x8 micro.
// ============================================================================
constexpr int GBM = 128, GBN = 128, GBK = 32;

template <int MODE>
__global__ __launch_bounds__(256) void gemm_nt(const float* __restrict__ Ain,
                                               const float* __restrict__ W,
                                               float* __restrict__ Cout) {
    constexpr int M = CM, N = CD, K = CD;
    const float* A = (MODE == 3) ? g_P : Ain;
    float* C = (MODE == 0) ? g_K : (MODE == 1) ? g_V : (MODE == 2) ? g_Sf : Cout;

    __shared__ __align__(16) float As[GBK][GBM];
    __shared__ __align__(16) float Bs[GBK][GBN];

    const int tid = threadIdx.x;
    const int m0 = blockIdx.y * GBM;
    const int n0 = blockIdx.x * GBN;
    const int tx = tid & 15;   // 16 col groups
    const int ty = tid >> 4;   // 16 row groups

    float acc[8][8];
#pragma unroll
    for (int i = 0; i < 8; i++)
#pragma unroll
        for (int j = 0; j < 8; j++) acc[i][j] = 0.f;

    for (int k0 = 0; k0 < K; k0 += GBK) {
        // ---- load A tile: 128 rows x 32 k, fully coalesced (8 thr = 1 row) --
#pragma unroll
        for (int it = 0; it < 4; it++) {
            int f = tid + it * 256;        // [0,1024) float4 index
            int row = f >> 3;              // 8 float4 per row
            int kq = (f & 7) * 4;
            float4 a4 = *(const float4*)(A + (size_t)(m0 + row) * K + k0 + kq);
            if (MODE == 3) {
                float4 s4 = *(const float4*)(g_Sf + (size_t)(m0 + row) * K + k0 + kq);
                a4.x += s4.x; a4.y += s4.y; a4.z += s4.z; a4.w += s4.w;
            }
            As[kq + 0][row] = a4.x;
            As[kq + 1][row] = a4.y;
            As[kq + 2][row] = a4.z;
            As[kq + 3][row] = a4.w;
        }
        // ---- load W tile: 128 n-rows x 32 k ---------------------------------
#pragma unroll
        for (int it = 0; it < 4; it++) {
            int f = tid + it * 256;
            int row = f >> 3;
            int kq = (f & 7) * 4;
            float4 b4 = *(const float4*)(W + (size_t)(n0 + row) * K + k0 + kq);
            Bs[kq + 0][row] = b4.x;
            Bs[kq + 1][row] = b4.y;
            Bs[kq + 2][row] = b4.z;
            Bs[kq + 3][row] = b4.w;
        }
        __syncthreads();

#pragma unroll
        for (int kk = 0; kk < GBK; kk++) {
            float a[8], b[8];
            *(float4*)&a[0] = *(const float4*)&As[kk][ty * 8];
            *(float4*)&a[4] = *(const float4*)&As[kk][ty * 8 + 4];
            *(float4*)&b[0] = *(const float4*)&Bs[kk][tx * 8];
            *(float4*)&b[4] = *(const float4*)&Bs[kk][tx * 8 + 4];
#pragma unroll
            for (int i = 0; i < 8; i++)
#pragma unroll
                for (int j = 0; j < 8; j++) acc[i][j] = fmaf(a[i], b[j], acc[i][j]);
        }
        __syncthreads();
    }

#pragma unroll
    for (int i = 0; i < 8; i++) {
        float* crow = C + (size_t)(m0 + ty * 8 + i) * N + n0 + tx * 8;
        *(float4*)(crow) = make_float4(acc[i][0], acc[i][1], acc[i][2], acc[i][3]);
        *(float4*)(crow + 4) = make_float4(acc[i][4], acc[i][5], acc[i][6], acc[i][7]);
    }
}

// ============================================================================
// Causal attention with Q == K:
//   scores = -K K^T / sqrt(hd), causal mask, softmax, @ V  -> g_P
// Block: 64 query rows x 32 key cols per iteration, online softmax.
// 256 threads: thread = (row i = tid>>2, quarter q = tid&3).
//   - Kq row cached in regs (32 dims per thread, butterfly shfl completes dot)
//   - each thread owns o[32] output dims (its quarter)
// smem tiles chunked [32][4][36] so the 4 q-groups hit distinct banks (float4).
// ============================================================================
__global__ __launch_bounds__(256) void attn_kernel() {
    const int qb = blockIdx.x;          // 32 query blocks
    const int bh = blockIdx.y;          // 16 (b,h) pairs
    const int b = bh / CH, h = bh % CH;
    const int q0 = qb * 64;

    const int tid = threadIdx.x;
    const int i = tid >> 2;             // row in q-block [0,64)
    const int q = tid & 3;              // dim quarter  [0,4)
    const int ig = q0 + i;              // global query index

    const float* Kbase = g_K + (size_t)b * CS * CD + h * CHD;
    const float* Vbase = g_V + (size_t)b * CS * CD + h * CHD;

    __shared__ __align__(16) float Kk_s[32][4][36];
    __shared__ __align__(16) float V_s[32][4][36];

    // cache this thread's quarter of the query-key row
    float kq[32];
#pragma unroll
    for (int u = 0; u < 8; u++) {
        float4 t4 = *(const float4*)(Kbase + (size_t)ig * CD + q * 32 + u * 4);
        kq[u * 4 + 0] = t4.x; kq[u * 4 + 1] = t4.y;
        kq[u * 4 + 2] = t4.z; kq[u * 4 + 3] = t4.w;
    }

    float o[32];
#pragma unroll
    for (int d = 0; d < 32; d++) o[d] = 0.f;
    float mi = -1e30f, li = 0.f;
    const float scale = 0.08838834764831845f;  // 1/sqrt(128)

    const int nkb = (q0 + 64) / 32;  // key blocks covering [0, q0+64)
    for (int kb = 0; kb < nkb; kb++) {
        const int k0 = kb * 32;
        // ---- cooperative load of Kk and V tiles (32 x 128) ------------------
#pragma unroll
        for (int it = 0; it < 4; it++) {
            int e = tid * 4 + it * 1024;         // float index in [0, 4096)
            int r = e >> 7, c = e & 127;
            float4 k4 = *(const float4*)(Kbase + (size_t)(k0 + r) * CD + c);
            float4 v4 = *(const float4*)(Vbase + (size_t)(k0 + r) * CD + c);
            *(float4*)&Kk_s[r][c >> 5][c & 31] = k4;
            *(float4*)&V_s[r][c >> 5][c & 31] = v4;
        }
        __syncthreads();

        // ---- scores for this thread's row (partial dot + butterfly) ---------
        float sv[32];
#pragma unroll
        for (int j = 0; j < 32; j++) {
            const float* kr = &Kk_s[j][q][0];
            float acc = 0.f;
#pragma unroll
            for (int u = 0; u < 8; u++) {
                float4 k4 = *(const float4*)(kr + u * 4);
                acc = fmaf(kq[u * 4 + 0], k4.x, acc);
                acc = fmaf(kq[u * 4 + 1], k4.y, acc);
                acc = fmaf(kq[u * 4 + 2], k4.z, acc);
                acc = fmaf(kq[u * 4 + 3], k4.w, acc);
            }
            acc += __shfl_xor_sync(0xffffffffu, acc, 1);
            acc += __shfl_xor_sync(0xffffffffu, acc, 2);
            sv[j] = (k0 + j <= ig) ? (-acc * scale) : -1e30f;
        }

        // ---- online softmax update ------------------------------------------
        float mnew = mi;
#pragma unroll
        for (int j = 0; j < 32; j++) mnew = fmaxf(mnew, sv[j]);
        float lsum = 0.f;
#pragma unroll
        for (int j = 0; j < 32; j++) {
            sv[j] = __expf(sv[j] - mnew);   // masked -> exp(-huge)=0
            lsum += sv[j];
        }
        const float alpha = __expf(mi - mnew);
        li = li * alpha + lsum;
#pragma unroll
        for (int d = 0; d < 32; d++) o[d] *= alpha;

        // ---- o += P @ V (thread's dim quarter) ------------------------------
#pragma unroll
        for (int j = 0; j < 32; j++) {
            const float p = sv[j];
            const float* vr = &V_s[j][q][0];
#pragma unroll
            for (int u = 0; u < 8; u++) {
                float4 v4 = *(const float4*)(vr + u * 4);
                o[u * 4 + 0] = fmaf(p, v4.x, o[u * 4 + 0]);
                o[u * 4 + 1] = fmaf(p, v4.y, o[u * 4 + 1]);
                o[u * 4 + 2] = fmaf(p, v4.z, o[u * 4 + 2]);
                o[u * 4 + 3] = fmaf(p, v4.w, o[u * 4 + 3]);
            }
        }
        mi = mnew;
        __syncthreads();
    }

    const float inv = 1.f / li;
    float* prow = g_P + (size_t)(b * CS + ig) * CD + h * CHD + q * 32;
#pragma unroll
    for (int u = 0; u < 8; u++) {
        *(float4*)(prow + u * 4) = make_float4(o[u * 4 + 0] * inv, o[u * 4 + 1] * inv,
                                               o[u * 4 + 2] * inv, o[u * 4 + 3] * inv);
    }
}

// ============================================================================
// launch
// ============================================================================
extern "C" void kernel_launch(void* const* d_in, const int* in_sizes, int n_in,
                              void* d_out, int out_size) {
    const float* x  = (const float*)d_in[0];
    const float* Wk = (const float*)d_in[1];
    const float* Wv = (const float*)d_in[2];
    const float* Ws = (const float*)d_in[3];
    const float* Wo = (const float*)d_in[4];
    float* out = (float*)d_out;

    dim3 gg(CD / GBN, CM / GBM);  // (8, 32)
    dim3 gb(256);

    gemm_nt<0><<<gg, gb>>>(x, Wk, nullptr);   // -> g_K
    gemm_nt<1><<<gg, gb>>>(x, Wv, nullptr);   // -> g_V
    gemm_nt<2><<<gg, gb>>>(x, Ws, nullptr);   // -> g_Sf

    attn_kernel<<<dim3(CS / 64, CB * CH), 256>>>();  // -> g_P

    gemm_nt<3><<<gg, gb>>>(nullptr, Wo, out);  // (g_P + g_Sf) @ Wo^T -> out
}

// round 4
// speedup vs baseline: 1.2154x; 1.2154x over previous
#include <cuda_runtime.h>
#include <cuda_bf16.h>
#include <cstdint>
#include <math.h>

// ---------------- problem constants ----------------
constexpr int CB = 2;        // batch
constexpr int CS = 2048;     // seq
constexpr int CD = 1024;     // model dim
constexpr int CH = 8;        // heads
constexpr int CHD = 128;     // head dim
constexpr int CM = CB * CS;  // 4096 rows

// ---------------- scratch (device globals; no allocations allowed) ----------
__device__ float g_K[CB * CS * CD];   // key projection  [B,S,D]
__device__ float g_V[CB * CS * CD];   // value projection
__device__ float g_Sf[CB * CS * CD];  // self_force = x @ Wself^T
__device__ float g_P[CB * CS * CD];   // pairwise (attention output)

// bf16 split operands
__device__ __nv_bfloat16 g_xh[CM * CD];      // A hi (x, later P+Sf)
__device__ __nv_bfloat16 g_xl[CM * CD];      // A lo
__device__ __nv_bfloat16 g_wh[4][CD * CD];   // W hi (k,v,self,out)
__device__ __nv_bfloat16 g_wl[4][CD * CD];   // W lo

// ============================================================================
// PTX helpers (family-common: sm_80+ instructions only — the harness's ptxas
// targets plain sm_103, so tcgen05/TMEM are unavailable)
// ============================================================================
__device__ __forceinline__ uint32_t smem_u32(const void* p) {
    uint32_t a;
    asm("{ .reg .u64 t; cvta.to.shared.u64 t, %1; cvt.u32.u64 %0, t; }" : "=r"(a) : "l"(p));
    return a;
}

__device__ __forceinline__ void cp16(uint32_t dst, const void* src) {
    asm volatile("cp.async.cg.shared.global [%0], [%1], 16;" :: "r"(dst), "l"(src) : "memory");
}
#define CP_COMMIT() asm volatile("cp.async.commit_group;" ::: "memory")

__device__ __forceinline__ void ldsm4(uint32_t* r, uint32_t addr) {
    asm volatile("ldmatrix.sync.aligned.m8n8.x4.shared.b16 {%0,%1,%2,%3}, [%4];"
                 : "=r"(r[0]), "=r"(r[1]), "=r"(r[2]), "=r"(r[3]) : "r"(addr));
}

__device__ __forceinline__ void mma16816(float* d, const uint32_t* a, const uint32_t* b) {
    asm volatile(
        "mma.sync.aligned.m16n8k16.row.col.f32.bf16.bf16.f32 "
        "{%0,%1,%2,%3}, {%4,%5,%6,%7}, {%8,%9}, {%0,%1,%2,%3};\n"
        : "+f"(d[0]), "+f"(d[1]), "+f"(d[2]), "+f"(d[3])
        : "r"(a[0]), "r"(a[1]), "r"(a[2]), "r"(a[3]), "r"(b[0]), "r"(b[1]));
}

// ============================================================================
// fp32 -> bf16 hi/lo split kernels
// ============================================================================
__device__ __forceinline__ void split4(float4 v, __nv_bfloat162* hi2, __nv_bfloat162* lo2,
                                       size_t i2) {
    __nv_bfloat16 h0 = __float2bfloat16_rn(v.x), h1 = __float2bfloat16_rn(v.y);
    __nv_bfloat16 h2 = __float2bfloat16_rn(v.z), h3 = __float2bfloat16_rn(v.w);
    __nv_bfloat16 l0 = __float2bfloat16_rn(v.x - __bfloat162float(h0));
    __nv_bfloat16 l1 = __float2bfloat16_rn(v.y - __bfloat162float(h1));
    __nv_bfloat16 l2 = __float2bfloat16_rn(v.z - __bfloat162float(h2));
    __nv_bfloat16 l3 = __float2bfloat16_rn(v.w - __bfloat162float(h3));
    hi2[i2]     = __nv_bfloat162(h0, h1);
    hi2[i2 + 1] = __nv_bfloat162(h2, h3);
    lo2[i2]     = __nv_bfloat162(l0, l1);
    lo2[i2 + 1] = __nv_bfloat162(l2, l3);
}

// split x (ADD=false) or g_P+g_Sf (ADD=true) into g_xh/g_xl.
template <bool ADD>
__global__ __launch_bounds__(256) void split_x(const float* __restrict__ src) {
    size_t i = (size_t)blockIdx.x * blockDim.x + threadIdx.x;  // float4 index
    const float4* s = ADD ? (const float4*)g_P : (const float4*)src;
    float4 v = s[i];
    if (ADD) {
        float4 t = ((const float4*)g_Sf)[i];
        v.x += t.x; v.y += t.y; v.z += t.z; v.w += t.w;
    }
    split4(v, (__nv_bfloat162*)g_xh, (__nv_bfloat162*)g_xl, i * 2);
}

template <int I>
__global__ __launch_bounds__(256) void split_w(const float* __restrict__ W) {
    size_t i = (size_t)blockIdx.x * blockDim.x + threadIdx.x;
    float4 v = ((const float4*)W)[i];
    split4(v, (__nv_bfloat162*)g_wh[I], (__nv_bfloat162*)g_wl[I], i * 2);
}

// ============================================================================
// HMMA bf16-split GEMM:  C[m,n] = sum_k A[m,k] * W[n,k]   (A @ W^T)
//   A = g_xh + g_xl, W = g_wh[MODE] + g_wl[MODE]
//   C ~= Ah*Wh + Ah*Wl + Al*Wh   (fp32 accumulate in registers)
// CTA: 128x128 tile, 256 threads (8 warps of 64x32), K chunk 32,
// double-buffered cp.async. Smem rows are 80B (64B data + 16B pad):
// granule index (5*row + chunk) mod 8 is a permutation -> conflict-free
// ldmatrix for any 8 consecutive rows.
// ============================================================================
constexpr int RSTRIDE = 80;                 // bytes per smem row (32 bf16 + pad)
constexpr int TILE_B = 128 * RSTRIDE;       // 10240 B per tile
constexpr int STAGE_B = 4 * TILE_B;         // Ah, Al, Bh, Bl
constexpr int G_SMEM = 2 * STAGE_B;         // 81920 B (double buffer)

template <int MODE>
__global__ __launch_bounds__(256, 2) void gemm_bf16(float* __restrict__ Cout) {
    extern __shared__ __align__(128) char smem[];
    const uint32_t sb = smem_u32(smem);
    const int tid = threadIdx.x, wid = tid >> 5, lane = tid & 31;
    const int m0 = blockIdx.y * 128, n0 = blockIdx.x * 128;
    const int wm = (wid >> 2) * 64;   // warp m offset (0 or 64)
    const int wn = (wid & 3) * 32;    // warp n offset (0,32,64,96)

    const __nv_bfloat16* Ah = g_xh;
    const __nv_bfloat16* Al = g_xl;
    const __nv_bfloat16* Bh = g_wh[MODE];
    const __nv_bfloat16* Bl = g_wl[MODE];
    float* C = (MODE == 0) ? g_K : (MODE == 1) ? g_V : (MODE == 2) ? g_Sf : Cout;

    float acc[4][4][4];
#pragma unroll
    for (int i = 0; i < 4; i++)
#pragma unroll
        for (int j = 0; j < 4; j++)
#pragma unroll
            for (int r = 0; r < 4; r++) acc[i][j][r] = 0.f;

    // per-thread load slots: 2 (row,chunk) pairs per tile
    const int lrow0 = tid >> 2, lc0 = tid & 3;          // rows 0..63
    const int lrow1 = (tid + 256) >> 2, lc1 = tid & 3;  // rows 64..127

#define LOAD_STAGE(s, k0)                                                          \
    do {                                                                           \
        uint32_t st_ = sb + (s) * STAGE_B;                                         \
        size_t gA0 = (size_t)(m0 + lrow0) * CD + (k0) + lc0 * 8;                   \
        size_t gA1 = (size_t)(m0 + lrow1) * CD + (k0) + lc1 * 8;                   \
        size_t gB0 = (size_t)(n0 + lrow0) * CD + (k0) + lc0 * 8;                   \
        size_t gB1 = (size_t)(n0 + lrow1) * CD + (k0) + lc1 * 8;                   \
        uint32_t s0 = lrow0 * RSTRIDE + lc0 * 16, s1 = lrow1 * RSTRIDE + lc1 * 16; \
        cp16(st_ + 0 * TILE_B + s0, Ah + gA0);                                     \
        cp16(st_ + 0 * TILE_B + s1, Ah + gA1);                                     \
        cp16(st_ + 1 * TILE_B + s0, Al + gA0);                                     \
        cp16(st_ + 1 * TILE_B + s1, Al + gA1);                                     \
        cp16(st_ + 2 * TILE_B + s0, Bh + gB0);                                     \
        cp16(st_ + 2 * TILE_B + s1, Bh + gB1);                                     \
        cp16(st_ + 3 * TILE_B + s0, Bl + gB0);                                     \
        cp16(st_ + 3 * TILE_B + s1, Bl + gB1);                                     \
        CP_COMMIT();                                                               \
    } while (0)

    LOAD_STAGE(0, 0);

    constexpr int NC = CD / 32;  // 32 K-chunks
    for (int c = 0; c < NC; c++) {
        if (c + 1 < NC) {
            LOAD_STAGE((c + 1) & 1, (c + 1) * 32);
            asm volatile("cp.async.wait_group 1;" ::: "memory");
        } else {
            asm volatile("cp.async.wait_group 0;" ::: "memory");
        }
        __syncthreads();

        const uint32_t st = sb + (c & 1) * STAGE_B;
#pragma unroll
        for (int h = 0; h < 2; h++) {  // two k16 steps per chunk
            // ---- B fragments: 2x ldmatrix.x4 each for Bh, Bl (4 n-tiles) ----
            uint32_t bh[8], bl[8];
#pragma unroll
            for (int j2 = 0; j2 < 2; j2++) {
                uint32_t off = (uint32_t)((wn + j2 * 16 + (lane & 15)) * RSTRIDE +
                                          (h * 2 + (lane >> 4)) * 16);
                ldsm4(bh + j2 * 4, st + 2 * TILE_B + off);
                ldsm4(bl + j2 * 4, st + 3 * TILE_B + off);
            }
#pragma unroll
            for (int i = 0; i < 4; i++) {  // 4 m-tiles
                uint32_t aoff = (uint32_t)((wm + i * 16 + (lane & 15)) * RSTRIDE +
                                           (h * 2 + (lane >> 4)) * 16);
                uint32_t ah[4], al[4];
                ldsm4(ah, st + 0 * TILE_B + aoff);
                ldsm4(al, st + 1 * TILE_B + aoff);
#pragma unroll
                for (int j = 0; j < 4; j++) {  // 4 n-tiles
                    uint32_t bh2[2] = {bh[(j >> 1) * 4 + (j & 1)], bh[(j >> 1) * 4 + 2 + (j & 1)]};
                    uint32_t bl2[2] = {bl[(j >> 1) * 4 + (j & 1)], bl[(j >> 1) * 4 + 2 + (j & 1)]};
                    mma16816(acc[i][j], ah, bh2);
                    mma16816(acc[i][j], ah, bl2);
                    mma16816(acc[i][j], al, bh2);
                }
            }
        }
        __syncthreads();
    }
#undef LOAD_STAGE

    // ---- epilogue: d-fragment rows lane>>2 and +8, cols (lane&3)*2 ----------
#pragma unroll
    for (int i = 0; i < 4; i++) {
        const int m = m0 + wm + i * 16 + (lane >> 2);
#pragma unroll
        for (int j = 0; j < 4; j++) {
            const int n = n0 + wn + j * 8 + (lane & 3) * 2;
            *(float2*)(C + (size_t)m * CD + n) = make_float2(acc[i][j][0], acc[i][j][1]);
            *(float2*)(C + (size_t)(m + 8) * CD + n) = make_float2(acc[i][j][2], acc[i][j][3]);
        }
    }
}

// ============================================================================
// Causal attention with Q == K (fp32):
//   scores = -K K^T / sqrt(hd), causal mask, softmax, @ V  -> g_P
// 64 q-rows x 32-key tiles, online softmax in 16-key sub-chunks (reg pressure).
// thread = (row i = tid>>2, quarter q = tid&3); kq/o in regs, shfl to finish dots.
// ============================================================================
__global__ __launch_bounds__(256, 2) void attn_kernel() {
    const int qb = blockIdx.x;
    const int bh = blockIdx.y;
    const int b = bh / CH, h = bh % CH;
    const int q0 = qb * 64;

    const int tid = threadIdx.x;
    const int i = tid >> 2;
    const int q = tid & 3;
    const int ig = q0 + i;

    const float* Kbase = g_K + (size_t)b * CS * CD + h * CHD;
    const float* Vbase = g_V + (size_t)b * CS * CD + h * CHD;

    __shared__ __align__(16) float Kk_s[32][4][36];
    __shared__ __align__(16) float V_s[32][4][36];

    float kq[32];
#pragma unroll
    for (int u = 0; u < 8; u++) {
        float4 t4 = *(const float4*)(Kbase + (size_t)ig * CD + q * 32 + u * 4);
        kq[u * 4 + 0] = t4.x; kq[u * 4 + 1] = t4.y;
        kq[u * 4 + 2] = t4.z; kq[u * 4 + 3] = t4.w;
    }

    float o[32];
#pragma unroll
    for (int d = 0; d < 32; d++) o[d] = 0.f;
    float mi = -1e30f, li = 0.f;
    const float scale = 0.08838834764831845f;  // 1/sqrt(128)

    const int nkb = (q0 + 64) / 32;
    for (int kb = 0; kb < nkb; kb++) {
        const int k0 = kb * 32;
#pragma unroll
        for (int it = 0; it < 4; it++) {
            int e = tid * 4 + it * 1024;
            int r = e >> 7, c = e & 127;
            float4 k4 = *(const float4*)(Kbase + (size_t)(k0 + r) * CD + c);
            float4 v4 = *(const float4*)(Vbase + (size_t)(k0 + r) * CD + c);
            *(float4*)&Kk_s[r][c >> 5][c & 31] = k4;
            *(float4*)&V_s[r][c >> 5][c & 31] = v4;
        }
        __syncthreads();

#pragma unroll
        for (int half = 0; half < 2; half++) {
            const int jb = half * 16;
            float sv[16];
#pragma unroll
            for (int j = 0; j < 16; j++) {
                const float* kr = &Kk_s[jb + j][q][0];
                float acc = 0.f;
#pragma unroll
                for (int u = 0; u < 8; u++) {
                    float4 k4 = *(const float4*)(kr + u * 4);
                    acc = fmaf(kq[u * 4 + 0], k4.x, acc);
                    acc = fmaf(kq[u * 4 + 1], k4.y, acc);
                    acc = fmaf(kq[u * 4 + 2], k4.z, acc);
                    acc = fmaf(kq[u * 4 + 3], k4.w, acc);
                }
                acc += __shfl_xor_sync(0xffffffffu, acc, 1);
                acc += __shfl_xor_sync(0xffffffffu, acc, 2);
                sv[j] = (k0 + jb + j <= ig) ? (-acc * scale) : -1e30f;
            }

            float mnew = mi;
#pragma unroll
            for (int j = 0; j < 16; j++) mnew = fmaxf(mnew, sv[j]);
            float lsum = 0.f;
#pragma unroll
            for (int j = 0; j < 16; j++) {
                sv[j] = __expf(sv[j] - mnew);
                lsum += sv[j];
            }
            const float alpha = __expf(mi - mnew);
            li = li * alpha + lsum;
#pragma unroll
            for (int d = 0; d < 32; d++) o[d] *= alpha;

#pragma unroll
            for (int j = 0; j < 16; j++) {
                const float p = sv[j];
                const float* vr = &V_s[jb + j][q][0];
#pragma unroll
                for (int u = 0; u < 8; u++) {
                    float4 v4 = *(const float4*)(vr + u * 4);
                    o[u * 4 + 0] = fmaf(p, v4.x, o[u * 4 + 0]);
                    o[u * 4 + 1] = fmaf(p, v4.y, o[u * 4 + 1]);
                    o[u * 4 + 2] = fmaf(p, v4.z, o[u * 4 + 2]);
                    o[u * 4 + 3] = fmaf(p, v4.w, o[u * 4 + 3]);
                }
            }
            mi = mnew;
        }
        __syncthreads();
    }

    const float inv = 1.f / li;
    float* prow = g_P + (size_t)(b * CS + ig) * CD + h * CHD + q * 32;
#pragma unroll
    for (int u = 0; u < 8; u++) {
        *(float4*)(prow + u * 4) = make_float4(o[u * 4 + 0] * inv, o[u * 4 + 1] * inv,
                                               o[u * 4 + 2] * inv, o[u * 4 + 3] * inv);
    }
}

// ============================================================================
// launch
// ============================================================================
extern "C" void kernel_launch(void* const* d_in, const int* in_sizes, int n_in,
                              void* d_out, int out_size) {
    const float* x  = (const float*)d_in[0];
    const float* Wk = (const float*)d_in[1];
    const float* Wv = (const float*)d_in[2];
    const float* Ws = (const float*)d_in[3];
    const float* Wo = (const float*)d_in[4];
    float* out = (float*)d_out;

    // stream-free, idempotent; safe during graph capture
    cudaFuncSetAttribute(gemm_bf16<0>, cudaFuncAttributeMaxDynamicSharedMemorySize, G_SMEM);
    cudaFuncSetAttribute(gemm_bf16<1>, cudaFuncAttributeMaxDynamicSharedMemorySize, G_SMEM);
    cudaFuncSetAttribute(gemm_bf16<2>, cudaFuncAttributeMaxDynamicSharedMemorySize, G_SMEM);
    cudaFuncSetAttribute(gemm_bf16<3>, cudaFuncAttributeMaxDynamicSharedMemorySize, G_SMEM);

    dim3 gg(CD / 128, CM / 128);   // (8, 32) = 256 CTAs
    const int XB = (CM * CD / 4) / 256;   // x-sized split blocks (float4/thread)
    const int WB = (CD * CD / 4) / 256;   // weight split blocks

    split_x<false><<<XB, 256>>>(x);
    split_w<0><<<WB, 256>>>(Wk);
    split_w<1><<<WB, 256>>>(Wv);
    split_w<2><<<WB, 256>>>(Ws);
    split_w<3><<<WB, 256>>>(Wo);

    gemm_bf16<0><<<gg, 256, G_SMEM>>>(nullptr);   // -> g_K
    gemm_bf16<1><<<gg, 256, G_SMEM>>>(nullptr);   // -> g_V
    gemm_bf16<2><<<gg, 256, G_SMEM>>>(nullptr);   // -> g_Sf

    attn_kernel<<<dim3(CS / 64, CB * CH), 256>>>();  // -> g_P

    split_x<true><<<XB, 256>>>(nullptr);          // (g_P + g_Sf) -> g_xh/g_xl
    gemm_bf16<3><<<gg, 256, G_SMEM>>>(out);       // @ Wo^T -> out
}

// round 5
// speedup vs baseline: 4.1162x; 3.3868x over previous
#include <cuda_runtime.h>
#include <cuda_bf16.h>
#include <cstdint>
#include <math.h>

// ---------------- problem constants ----------------
constexpr int CB = 2;        // batch
constexpr int CS = 2048;     // seq
constexpr int CD = 1024;     // model dim
constexpr int CH = 8;        // heads
constexpr int CHD = 128;     // head dim
constexpr int CM = CB * CS;  // 4096 rows

// ---------------- scratch (device globals; no allocations allowed) ----------
__device__ float g_K[CB * CS * CD];   // key projection  [B,S,D] fp32
__device__ float g_V[CB * CS * CD];   // value projection fp32
__device__ float g_Sf[CB * CS * CD];  // self_force = x @ Wself^T
__device__ float g_P[CB * CS * CD];   // pairwise (attention output)

// bf16 split operands for GEMMs
__device__ __nv_bfloat16 g_xh[CM * CD];
__device__ __nv_bfloat16 g_xl[CM * CD];
__device__ __nv_bfloat16 g_wh[4][CD * CD];
__device__ __nv_bfloat16 g_wl[4][CD * CD];

// bf16 K/V for attention
__device__ __nv_bfloat16 g_Kh[CB * CS * CD];
__device__ __nv_bfloat16 g_Kl[CB * CS * CD];
__device__ __nv_bfloat16 g_Vb[CB * CS * CD];

// ============================================================================
// PTX helpers (family-common sm_80+ only; tcgen05 unavailable on this ptxas)
// ============================================================================
__device__ __forceinline__ uint32_t smem_u32(const void* p) {
    uint32_t a;
    asm("{ .reg .u64 t; cvta.to.shared.u64 t, %1; cvt.u32.u64 %0, t; }" : "=r"(a) : "l"(p));
    return a;
}
__device__ __forceinline__ void cp16(uint32_t dst, const void* src) {
    asm volatile("cp.async.cg.shared.global [%0], [%1], 16;" :: "r"(dst), "l"(src) : "memory");
}
#define CP_COMMIT() asm volatile("cp.async.commit_group;" ::: "memory")

__device__ __forceinline__ void ldsm4(uint32_t* r, uint32_t addr) {
    asm volatile("ldmatrix.sync.aligned.m8n8.x4.shared.b16 {%0,%1,%2,%3}, [%4];"
                 : "=r"(r[0]), "=r"(r[1]), "=r"(r[2]), "=r"(r[3]) : "r"(addr));
}
__device__ __forceinline__ void ldsm4t(uint32_t* r, uint32_t addr) {
    asm volatile("ldmatrix.sync.aligned.m8n8.x4.trans.shared.b16 {%0,%1,%2,%3}, [%4];"
                 : "=r"(r[0]), "=r"(r[1]), "=r"(r[2]), "=r"(r[3]) : "r"(addr));
}
__device__ __forceinline__ void mma16816(float* d, const uint32_t* a, const uint32_t* b) {
    asm volatile(
        "mma.sync.aligned.m16n8k16.row.col.f32.bf16.bf16.f32 "
        "{%0,%1,%2,%3}, {%4,%5,%6,%7}, {%8,%9}, {%0,%1,%2,%3};\n"
        : "+f"(d[0]), "+f"(d[1]), "+f"(d[2]), "+f"(d[3])
        : "r"(a[0]), "r"(a[1]), "r"(a[2]), "r"(a[3]), "r"(b[0]), "r"(b[1]));
}

// ============================================================================
// fp32 -> bf16 hi/lo split kernels
// ============================================================================
__device__ __forceinline__ void split4(float4 v, __nv_bfloat162* hi2, __nv_bfloat162* lo2,
                                       size_t i2) {
    __nv_bfloat16 h0 = __float2bfloat16_rn(v.x), h1 = __float2bfloat16_rn(v.y);
    __nv_bfloat16 h2 = __float2bfloat16_rn(v.z), h3 = __float2bfloat16_rn(v.w);
    __nv_bfloat16 l0 = __float2bfloat16_rn(v.x - __bfloat162float(h0));
    __nv_bfloat16 l1 = __float2bfloat16_rn(v.y - __bfloat162float(h1));
    __nv_bfloat16 l2 = __float2bfloat16_rn(v.z - __bfloat162float(h2));
    __nv_bfloat16 l3 = __float2bfloat16_rn(v.w - __bfloat162float(h3));
    hi2[i2]     = __nv_bfloat162(h0, h1);
    hi2[i2 + 1] = __nv_bfloat162(h2, h3);
    lo2[i2]     = __nv_bfloat162(l0, l1);
    lo2[i2 + 1] = __nv_bfloat162(l2, l3);
}

template <bool ADD>
__global__ __launch_bounds__(256) void split_x(const float* __restrict__ src) {
    size_t i = (size_t)blockIdx.x * blockDim.x + threadIdx.x;
    const float4* s = ADD ? (const float4*)g_P : (const float4*)src;
    float4 v = s[i];
    if (ADD) {
        float4 t = ((const float4*)g_Sf)[i];
        v.x += t.x; v.y += t.y; v.z += t.z; v.w += t.w;
    }
    split4(v, (__nv_bfloat162*)g_xh, (__nv_bfloat162*)g_xl, i * 2);
}

template <int I>
__global__ __launch_bounds__(256) void split_w(const float* __restrict__ W) {
    size_t i = (size_t)blockIdx.x * blockDim.x + threadIdx.x;
    float4 v = ((const float4*)W)[i];
    split4(v, (__nv_bfloat162*)g_wh[I], (__nv_bfloat162*)g_wl[I], i * 2);
}

// K -> (Kh, Kl) split; V -> bf16
__global__ __launch_bounds__(256) void conv_kv() {
    size_t i = (size_t)blockIdx.x * blockDim.x + threadIdx.x;
    float4 k4 = ((const float4*)g_K)[i];
    split4(k4, (__nv_bfloat162*)g_Kh, (__nv_bfloat162*)g_Kl, i * 2);
    float4 v4 = ((const float4*)g_V)[i];
    ((__nv_bfloat162*)g_Vb)[i * 2]     = __floats2bfloat162_rn(v4.x, v4.y);
    ((__nv_bfloat162*)g_Vb)[i * 2 + 1] = __floats2bfloat162_rn(v4.z, v4.w);
}

// ============================================================================
// HMMA bf16-split GEMM (verified round 4):  C = A @ W^T
// ============================================================================
constexpr int RSTRIDE = 80;
constexpr int TILE_B = 128 * RSTRIDE;
constexpr int STAGE_B = 4 * TILE_B;
constexpr int G_SMEM = 2 * STAGE_B;

template <int MODE>
__global__ __launch_bounds__(256, 2) void gemm_bf16(float* __restrict__ Cout) {
    extern __shared__ __align__(128) char smem[];
    const uint32_t sb = smem_u32(smem);
    const int tid = threadIdx.x, wid = tid >> 5, lane = tid & 31;
    const int m0 = blockIdx.y * 128, n0 = blockIdx.x * 128;
    const int wm = (wid >> 2) * 64;
    const int wn = (wid & 3) * 32;

    const __nv_bfloat16* Ah = g_xh;
    const __nv_bfloat16* Al = g_xl;
    const __nv_bfloat16* Bh = g_wh[MODE];
    const __nv_bfloat16* Bl = g_wl[MODE];
    float* C = (MODE == 0) ? g_K : (MODE == 1) ? g_V : (MODE == 2) ? g_Sf : Cout;

    float acc[4][4][4];
#pragma unroll
    for (int i = 0; i < 4; i++)
#pragma unroll
        for (int j = 0; j < 4; j++)
#pragma unroll
            for (int r = 0; r < 4; r++) acc[i][j][r] = 0.f;

    const int lrow0 = tid >> 2, lc0 = tid & 3;
    const int lrow1 = (tid + 256) >> 2, lc1 = tid & 3;

#define LOAD_STAGE(s, k0)                                                          \
    do {                                                                           \
        uint32_t st_ = sb + (s) * STAGE_B;                                         \
        size_t gA0 = (size_t)(m0 + lrow0) * CD + (k0) + lc0 * 8;                   \
        size_t gA1 = (size_t)(m0 + lrow1) * CD + (k0) + lc1 * 8;                   \
        size_t gB0 = (size_t)(n0 + lrow0) * CD + (k0) + lc0 * 8;                   \
        size_t gB1 = (size_t)(n0 + lrow1) * CD + (k0) + lc1 * 8;                   \
        uint32_t s0 = lrow0 * RSTRIDE + lc0 * 16, s1 = lrow1 * RSTRIDE + lc1 * 16; \
        cp16(st_ + 0 * TILE_B + s0, Ah + gA0);                                     \
        cp16(st_ + 0 * TILE_B + s1, Ah + gA1);                                     \
        cp16(st_ + 1 * TILE_B + s0, Al + gA0);                                     \
        cp16(st_ + 1 * TILE_B + s1, Al + gA1);                                     \
        cp16(st_ + 2 * TILE_B + s0, Bh + gB0);                                     \
        cp16(st_ + 2 * TILE_B + s1, Bh + gB1);                                     \
        cp16(st_ + 3 * TILE_B + s0, Bl + gB0);                                     \
        cp16(st_ + 3 * TILE_B + s1, Bl + gB1);                                     \
        CP_COMMIT();                                                               \
    } while (0)

    LOAD_STAGE(0, 0);

    constexpr int NC = CD / 32;
    for (int c = 0; c < NC; c++) {
        if (c + 1 < NC) {
            LOAD_STAGE((c + 1) & 1, (c + 1) * 32);
            asm volatile("cp.async.wait_group 1;" ::: "memory");
        } else {
            asm volatile("cp.async.wait_group 0;" ::: "memory");
        }
        __syncthreads();

        const uint32_t st = sb + (c & 1) * STAGE_B;
#pragma unroll
        for (int h = 0; h < 2; h++) {
            uint32_t bh[8], bl[8];
#pragma unroll
            for (int j2 = 0; j2 < 2; j2++) {
                uint32_t off = (uint32_t)((wn + j2 * 16 + (lane & 15)) * RSTRIDE +
                                          (h * 2 + (lane >> 4)) * 16);
                ldsm4(bh + j2 * 4, st + 2 * TILE_B + off);
                ldsm4(bl + j2 * 4, st + 3 * TILE_B + off);
            }
#pragma unroll
            for (int i = 0; i < 4; i++) {
                uint32_t aoff = (uint32_t)((wm + i * 16 + (lane & 15)) * RSTRIDE +
                                           (h * 2 + (lane >> 4)) * 16);
                uint32_t ah[4], al[4];
                ldsm4(ah, st + 0 * TILE_B + aoff);
                ldsm4(al, st + 1 * TILE_B + aoff);
#pragma unroll
                for (int j = 0; j < 4; j++) {
                    uint32_t bh2[2] = {bh[(j >> 1) * 4 + (j & 1)], bh[(j >> 1) * 4 + 2 + (j & 1)]};
                    uint32_t bl2[2] = {bl[(j >> 1) * 4 + (j & 1)], bl[(j >> 1) * 4 + 2 + (j & 1)]};
                    mma16816(acc[i][j], ah, bh2);
                    mma16816(acc[i][j], ah, bl2);
                    mma16816(acc[i][j], al, bh2);
                }
            }
        }
        __syncthreads();
    }
#undef LOAD_STAGE

#pragma unroll
    for (int i = 0; i < 4; i++) {
        const int m = m0 + wm + i * 16 + (lane >> 2);
#pragma unroll
        for (int j = 0; j < 4; j++) {
            const int n = n0 + wn + j * 8 + (lane & 3) * 2;
            *(float2*)(C + (size_t)m * CD + n) = make_float2(acc[i][j][0], acc[i][j][1]);
            *(float2*)(C + (size_t)(m + 8) * CD + n) = make_float2(acc[i][j][2], acc[i][j][3]);
        }
    }
}

// ============================================================================
// FA2-style causal attention on HMMA (Q == K):
//   S = -(K K^T)/sqrt(128) with 3-term bf16 split, softmax online, P@V bf16.
// CTA: one (b,h), 64 q-rows; 4 warps x 16 rows; key tiles of 64.
// Smem rows: 128 bf16 = 256B + 16B pad = 272B (17 granules, odd -> conflict-free).
// ============================================================================
constexpr int A_RS = 272;             // bytes per smem row
constexpr int A_TILE = 64 * A_RS;     // 17408 B
constexpr int A_SMEM = 5 * A_TILE;    // Qh Ql Kh Kl V = 87040 B

__global__ __launch_bounds__(128, 2) void fattn() {
    extern __shared__ __align__(128) char smem[];
    const uint32_t sb = smem_u32(smem);
    const uint32_t SQH = 0, SQL = A_TILE, SKH = 2 * A_TILE, SKL = 3 * A_TILE, SVB = 4 * A_TILE;

    const int qb = (int)(gridDim.x - 1 - blockIdx.x);  // heaviest first
    const int bh = blockIdx.y;
    const int b = bh >> 3, h = bh & 7;
    const int q0 = qb * 64;

    const int tid = threadIdx.x, wid = tid >> 5, lane = tid & 31;

    const __nv_bfloat16* Khg = g_Kh + (size_t)b * CS * CD + h * CHD;
    const __nv_bfloat16* Klg = g_Kl + (size_t)b * CS * CD + h * CHD;
    const __nv_bfloat16* Vbg = g_Vb + (size_t)b * CS * CD + h * CHD;

    // ---- load Q tiles (hi/lo): 64 rows x 16 granules each -------------------
    for (int t = tid; t < 64 * 16; t += 128) {
        int row = t >> 4, g = t & 15;
        uint32_t so = (uint32_t)(row * A_RS + g * 16);
        cp16(sb + SQH + so, Khg + (size_t)(q0 + row) * CD + g * 8);
        cp16(sb + SQL + so, Klg + (size_t)(q0 + row) * CD + g * 8);
    }
    CP_COMMIT();

    float o[16][4];
#pragma unroll
    for (int t = 0; t < 16; t++)
#pragma unroll
        for (int r = 0; r < 4; r++) o[t][r] = 0.f;
    float m0r = -1e30f, m1r = -1e30f, l0 = 0.f, l1 = 0.f;
    const float scale = 0.08838834764831845f;  // 1/sqrt(128)

    for (int kb = 0; kb <= qb; kb++) {
        const int k0 = kb * 64;
        __syncthreads();  // previous compute done before overwriting K/V
        for (int t = tid; t < 64 * 16; t += 128) {
            int row = t >> 4, g = t & 15;
            uint32_t so = (uint32_t)(row * A_RS + g * 16);
            cp16(sb + SKH + so, Khg + (size_t)(k0 + row) * CD + g * 8);
            cp16(sb + SKL + so, Klg + (size_t)(k0 + row) * CD + g * 8);
            cp16(sb + SVB + so, Vbg + (size_t)(k0 + row) * CD + g * 8);
        }
        CP_COMMIT();
        asm volatile("cp.async.wait_group 0;" ::: "memory");
        __syncthreads();

        // ---- scores: 16 q-rows x 64 keys per warp, 3-term bf16 split --------
        float s[8][4];
#pragma unroll
        for (int j = 0; j < 8; j++)
#pragma unroll
            for (int r = 0; r < 4; r++) s[j][r] = 0.f;

#pragma unroll
        for (int ks = 0; ks < 8; ks++) {  // hd k16 steps
            uint32_t qoff = (uint32_t)((wid * 16 + (lane & 15)) * A_RS + ks * 32 +
                                       (lane >> 4) * 16);
            uint32_t qh[4], ql[4];
            ldsm4(qh, sb + SQH + qoff);
            ldsm4(ql, sb + SQL + qoff);
            uint32_t khf[16], klf[16];
#pragma unroll
            for (int j4 = 0; j4 < 4; j4++) {
                uint32_t koff = (uint32_t)((j4 * 16 + (lane & 15)) * A_RS + ks * 32 +
                                           (lane >> 4) * 16);
                ldsm4(khf + j4 * 4, sb + SKH + koff);
                ldsm4(klf + j4 * 4, sb + SKL + koff);
            }
#pragma unroll
            for (int j = 0; j < 8; j++) {
                uint32_t bh2[2] = {khf[(j >> 1) * 4 + (j & 1)], khf[(j >> 1) * 4 + 2 + (j & 1)]};
                uint32_t bl2[2] = {klf[(j >> 1) * 4 + (j & 1)], klf[(j >> 1) * 4 + 2 + (j & 1)]};
                mma16816(s[j], qh, bh2);
                mma16816(s[j], qh, bl2);
                mma16816(s[j], ql, bh2);
            }
        }

        // negate + scale (+ causal mask on diagonal tile)
        const int r0l = wid * 16 + (lane >> 2);  // local q row (lower half)
#pragma unroll
        for (int j = 0; j < 8; j++) {
#pragma unroll
            for (int r = 0; r < 4; r++) s[j][r] = -s[j][r] * scale;
            if (kb == qb) {
                int cl = j * 8 + (lane & 3) * 2;
                if (cl > r0l) s[j][0] = -1e30f;
                if (cl + 1 > r0l) s[j][1] = -1e30f;
                if (cl > r0l + 8) s[j][2] = -1e30f;
                if (cl + 1 > r0l + 8) s[j][3] = -1e30f;
            }
        }

        // ---- online softmax --------------------------------------------------
        float mx0 = -1e30f, mx1 = -1e30f;
#pragma unroll
        for (int j = 0; j < 8; j++) {
            mx0 = fmaxf(mx0, fmaxf(s[j][0], s[j][1]));
            mx1 = fmaxf(mx1, fmaxf(s[j][2], s[j][3]));
        }
        mx0 = fmaxf(mx0, __shfl_xor_sync(0xffffffffu, mx0, 1));
        mx0 = fmaxf(mx0, __shfl_xor_sync(0xffffffffu, mx0, 2));
        mx1 = fmaxf(mx1, __shfl_xor_sync(0xffffffffu, mx1, 1));
        mx1 = fmaxf(mx1, __shfl_xor_sync(0xffffffffu, mx1, 2));
        const float mn0 = fmaxf(m0r, mx0), mn1 = fmaxf(m1r, mx1);
        const float a0 = __expf(m0r - mn0), a1 = __expf(m1r - mn1);
        float sum0 = 0.f, sum1 = 0.f;
#pragma unroll
        for (int j = 0; j < 8; j++) {
            s[j][0] = __expf(s[j][0] - mn0);
            s[j][1] = __expf(s[j][1] - mn0);
            s[j][2] = __expf(s[j][2] - mn1);
            s[j][3] = __expf(s[j][3] - mn1);
            sum0 += s[j][0] + s[j][1];
            sum1 += s[j][2] + s[j][3];
        }
        sum0 += __shfl_xor_sync(0xffffffffu, sum0, 1);
        sum0 += __shfl_xor_sync(0xffffffffu, sum0, 2);
        sum1 += __shfl_xor_sync(0xffffffffu, sum1, 1);
        sum1 += __shfl_xor_sync(0xffffffffu, sum1, 2);
        l0 = l0 * a0 + sum0;
        l1 = l1 * a1 + sum1;
        m0r = mn0; m1r = mn1;
#pragma unroll
        for (int t = 0; t < 16; t++) {
            o[t][0] *= a0; o[t][1] *= a0; o[t][2] *= a1; o[t][3] *= a1;
        }

        // ---- o += P @ V ------------------------------------------------------
#pragma unroll
        for (int kg = 0; kg < 4; kg++) {  // 16-key groups
            uint32_t pa[4];
            {
                __nv_bfloat162 t0 = __floats2bfloat162_rn(s[2 * kg][0], s[2 * kg][1]);
                __nv_bfloat162 t1 = __floats2bfloat162_rn(s[2 * kg][2], s[2 * kg][3]);
                __nv_bfloat162 t2 = __floats2bfloat162_rn(s[2 * kg + 1][0], s[2 * kg + 1][1]);
                __nv_bfloat162 t3 = __floats2bfloat162_rn(s[2 * kg + 1][2], s[2 * kg + 1][3]);
                pa[0] = *(uint32_t*)&t0; pa[1] = *(uint32_t*)&t1;
                pa[2] = *(uint32_t*)&t2; pa[3] = *(uint32_t*)&t3;
            }
#pragma unroll
            for (int n2 = 0; n2 < 8; n2++) {  // hd 16-col groups
                uint32_t voff = (uint32_t)((kg * 16 + (lane & 15)) * A_RS + n2 * 32 +
                                           (lane >> 4) * 16);
                uint32_t vf[4];
                ldsm4t(vf, sb + SVB + voff);
                uint32_t b0[2] = {vf[0], vf[1]};
                uint32_t b1[2] = {vf[2], vf[3]};
                mma16816(o[2 * n2], pa, b0);
                mma16816(o[2 * n2 + 1], pa, b1);
            }
        }
    }

    // ---- epilogue: normalize and store -------------------------------------
    const float inv0 = 1.f / l0, inv1 = 1.f / l1;
    const int row0 = q0 + wid * 16 + (lane >> 2);
#pragma unroll
    for (int t = 0; t < 16; t++) {
        const int col = h * CHD + t * 8 + (lane & 3) * 2;
        *(float2*)(g_P + (size_t)(b * CS + row0) * CD + col) =
            make_float2(o[t][0] * inv0, o[t][1] * inv0);
        *(float2*)(g_P + (size_t)(b * CS + row0 + 8) * CD + col) =
            make_float2(o[t][2] * inv1, o[t][3] * inv1);
    }
}

// ============================================================================
// launch
// ============================================================================
extern "C" void kernel_launch(void* const* d_in, const int* in_sizes, int n_in,
                              void* d_out, int out_size) {
    const float* x  = (const float*)d_in[0];
    const float* Wk = (const float*)d_in[1];
    const float* Wv = (const float*)d_in[2];
    const float* Ws = (const float*)d_in[3];
    const float* Wo = (const float*)d_in[4];
    float* out = (float*)d_out;

    cudaFuncSetAttribute(gemm_bf16<0>, cudaFuncAttributeMaxDynamicSharedMemorySize, G_SMEM);
    cudaFuncSetAttribute(gemm_bf16<1>, cudaFuncAttributeMaxDynamicSharedMemorySize, G_SMEM);
    cudaFuncSetAttribute(gemm_bf16<2>, cudaFuncAttributeMaxDynamicSharedMemorySize, G_SMEM);
    cudaFuncSetAttribute(gemm_bf16<3>, cudaFuncAttributeMaxDynamicSharedMemorySize, G_SMEM);
    cudaFuncSetAttribute(fattn, cudaFuncAttributeMaxDynamicSharedMemorySize, A_SMEM);

    dim3 gg(CD / 128, CM / 128);
    const int XB = (CM * CD / 4) / 256;
    const int WB = (CD * CD / 4) / 256;

    split_x<false><<<XB, 256>>>(x);
    split_w<0><<<WB, 256>>>(Wk);
    split_w<1><<<WB, 256>>>(Wv);
    split_w<2><<<WB, 256>>>(Ws);
    split_w<3><<<WB, 256>>>(Wo);

    gemm_bf16<0><<<gg, 256, G_SMEM>>>(nullptr);   // -> g_K
    gemm_bf16<1><<<gg, 256, G_SMEM>>>(nullptr);   // -> g_V
    gemm_bf16<2><<<gg, 256, G_SMEM>>>(nullptr);   // -> g_Sf

    conv_kv<<<(CM * CD / 4) / 256, 256>>>();      // K/V -> bf16 (hi/lo, V)

    fattn<<<dim3(CS / 64, CB * CH), 128, A_SMEM>>>();  // -> g_P

    split_x<true><<<XB, 256>>>(nullptr);          // (g_P + g_Sf) -> g_xh/g_xl
    gemm_bf16<3><<<gg, 256, G_SMEM>>>(out);       // @ Wo^T -> out
}

// round 6
// speedup vs baseline: 4.3513x; 1.0571x over previous
#include <cuda_runtime.h>
#include <cuda_bf16.h>
#include <cstdint>
#include <math.h>

// ---------------- problem constants ----------------
constexpr int CB = 2;        // batch
constexpr int CS = 2048;     // seq
constexpr int CD = 1024;     // model dim
constexpr int CH = 8;        // heads
constexpr int CHD = 128;     // head dim
constexpr int CM = CB * CS;  // 4096 rows

// ---------------- scratch (device globals; no allocations allowed) ----------
__device__ float g_Sf[CB * CS * CD];  // self_force = x @ Wself^T (fp32)

// bf16 split operands for GEMMs (A side; reused: x, then P+Sf)
__device__ __nv_bfloat16 g_xh[CM * CD];
__device__ __nv_bfloat16 g_xl[CM * CD];
__device__ __nv_bfloat16 g_wh[4][CD * CD];
__device__ __nv_bfloat16 g_wl[4][CD * CD];

// bf16 K/V for attention (written directly by GEMM epilogues)
__device__ __nv_bfloat16 g_Kh[CB * CS * CD];
__device__ __nv_bfloat16 g_Kl[CB * CS * CD];
__device__ __nv_bfloat16 g_Vb[CB * CS * CD];

// ============================================================================
// PTX helpers (family-common sm_80+ only; tcgen05 unavailable on this ptxas)
// ============================================================================
__device__ __forceinline__ uint32_t smem_u32(const void* p) {
    uint32_t a;
    asm("{ .reg .u64 t; cvta.to.shared.u64 t, %1; cvt.u32.u64 %0, t; }" : "=r"(a) : "l"(p));
    return a;
}
__device__ __forceinline__ void cp16(uint32_t dst, const void* src) {
    asm volatile("cp.async.cg.shared.global [%0], [%1], 16;" :: "r"(dst), "l"(src) : "memory");
}
#define CP_COMMIT() asm volatile("cp.async.commit_group;" ::: "memory")

__device__ __forceinline__ void ldsm4(uint32_t* r, uint32_t addr) {
    asm volatile("ldmatrix.sync.aligned.m8n8.x4.shared.b16 {%0,%1,%2,%3}, [%4];"
                 : "=r"(r[0]), "=r"(r[1]), "=r"(r[2]), "=r"(r[3]) : "r"(addr));
}
__device__ __forceinline__ void ldsm4t(uint32_t* r, uint32_t addr) {
    asm volatile("ldmatrix.sync.aligned.m8n8.x4.trans.shared.b16 {%0,%1,%2,%3}, [%4];"
                 : "=r"(r[0]), "=r"(r[1]), "=r"(r[2]), "=r"(r[3]) : "r"(addr));
}
__device__ __forceinline__ void mma16816(float* d, const uint32_t* a, const uint32_t* b) {
    asm volatile(
        "mma.sync.aligned.m16n8k16.row.col.f32.bf16.bf16.f32 "
        "{%0,%1,%2,%3}, {%4,%5,%6,%7}, {%8,%9}, {%0,%1,%2,%3};\n"
        : "+f"(d[0]), "+f"(d[1]), "+f"(d[2]), "+f"(d[3])
        : "r"(a[0]), "r"(a[1]), "r"(a[2]), "r"(a[3]), "r"(b[0]), "r"(b[1]));
}

// ---- fp32 -> bf16 hi/lo helpers --------------------------------------------
__device__ __forceinline__ void split4(float4 v, __nv_bfloat162* hi2, __nv_bfloat162* lo2,
                                       size_t i2) {
    __nv_bfloat16 h0 = __float2bfloat16_rn(v.x), h1 = __float2bfloat16_rn(v.y);
    __nv_bfloat16 h2 = __float2bfloat16_rn(v.z), h3 = __float2bfloat16_rn(v.w);
    __nv_bfloat16 l0 = __float2bfloat16_rn(v.x - __bfloat162float(h0));
    __nv_bfloat16 l1 = __float2bfloat16_rn(v.y - __bfloat162float(h1));
    __nv_bfloat16 l2 = __float2bfloat16_rn(v.z - __bfloat162float(h2));
    __nv_bfloat16 l3 = __float2bfloat16_rn(v.w - __bfloat162float(h3));
    hi2[i2]     = __nv_bfloat162(h0, h1);
    hi2[i2 + 1] = __nv_bfloat162(h2, h3);
    lo2[i2]     = __nv_bfloat162(l0, l1);
    lo2[i2 + 1] = __nv_bfloat162(l2, l3);
}
// split two scalars and store packed hi/lo pairs at H[off],L[off]
__device__ __forceinline__ void store_split2(__nv_bfloat16* H, __nv_bfloat16* L,
                                             size_t off, float a, float b) {
    __nv_bfloat16 h0 = __float2bfloat16_rn(a), h1 = __float2bfloat16_rn(b);
    __nv_bfloat16 l0 = __float2bfloat16_rn(a - __bfloat162float(h0));
    __nv_bfloat16 l1 = __float2bfloat16_rn(b - __bfloat162float(h1));
    *(__nv_bfloat162*)(H + off) = __nv_bfloat162(h0, h1);
    *(__nv_bfloat162*)(L + off) = __nv_bfloat162(l0, l1);
}

// ============================================================================
// prep: one kernel splitting x and all 4 weights into bf16 hi/lo
// ============================================================================
constexpr size_t XQ = (size_t)CM * CD / 4;   // float4 count of x
constexpr size_t WQ = (size_t)CD * CD / 4;   // float4 count of one weight
__global__ __launch_bounds__(256) void prep(const float* __restrict__ x,
                                            const float* __restrict__ Wk,
                                            const float* __restrict__ Wv,
                                            const float* __restrict__ Ws,
                                            const float* __restrict__ Wo) {
    size_t i = (size_t)blockIdx.x * 256 + threadIdx.x;
    if (i < XQ) {
        split4(((const float4*)x)[i], (__nv_bfloat162*)g_xh, (__nv_bfloat162*)g_xl, i * 2);
    } else {
        size_t j = i - XQ;
        int w = (int)(j / WQ);
        size_t o = j % WQ;
        const float* W = (w == 0) ? Wk : (w == 1) ? Wv : (w == 2) ? Ws : Wo;
        split4(((const float4*)W)[o], (__nv_bfloat162*)g_wh[w], (__nv_bfloat162*)g_wl[w], o * 2);
    }
}

// ============================================================================
// HMMA bf16-split GEMM core (verified R4/R5):  C = A @ W^T, 128x128 CTA tile
// gemm3: modes 0(K->Kh/Kl) 1(V->Vb) 2(Sf fp32) in ONE launch, grid (24, 32)
// gemm_out: final (P+Sf) @ Wout^T -> out fp32
// ============================================================================
constexpr int RSTRIDE = 80;
constexpr int TILE_B = 128 * RSTRIDE;
constexpr int STAGE_B = 4 * TILE_B;
constexpr int G_SMEM = 2 * STAGE_B;

#define GEMM_CORE(Ah_, Al_, Bh_, Bl_)                                              \
    float acc[4][4][4];                                                            \
    _Pragma("unroll") for (int i = 0; i < 4; i++)                                  \
        _Pragma("unroll") for (int j = 0; j < 4; j++)                              \
            _Pragma("unroll") for (int r = 0; r < 4; r++) acc[i][j][r] = 0.f;      \
    const int lrow0 = tid >> 2, lc0 = tid & 3;                                     \
    const int lrow1 = (tid + 256) >> 2, lc1 = tid & 3;                             \
    {                                                                              \
        uint32_t st_ = sb;                                                         \
        size_t gA0 = (size_t)(m0 + lrow0) * CD + lc0 * 8;                          \
        size_t gA1 = (size_t)(m0 + lrow1) * CD + lc1 * 8;                          \
        size_t gB0 = (size_t)(n0 + lrow0) * CD + lc0 * 8;                          \
        size_t gB1 = (size_t)(n0 + lrow1) * CD + lc1 * 8;                          \
        uint32_t s0 = lrow0 * RSTRIDE + lc0 * 16, s1 = lrow1 * RSTRIDE + lc1 * 16; \
        cp16(st_ + 0 * TILE_B + s0, Ah_ + gA0);                                    \
        cp16(st_ + 0 * TILE_B + s1, Ah_ + gA1);                                    \
        cp16(st_ + 1 * TILE_B + s0, Al_ + gA0);                                    \
        cp16(st_ + 1 * TILE_B + s1, Al_ + gA1);                                    \
        cp16(st_ + 2 * TILE_B + s0, Bh_ + gB0);                                    \
        cp16(st_ + 2 * TILE_B + s1, Bh_ + gB1);                                    \
        cp16(st_ + 3 * TILE_B + s0, Bl_ + gB0);                                    \
        cp16(st_ + 3 * TILE_B + s1, Bl_ + gB1);                                    \
        CP_COMMIT();                                                               \
    }                                                                              \
    constexpr int NC = CD / 32;                                                    \
    for (int c = 0; c < NC; c++) {                                                 \
        if (c + 1 < NC) {                                                          \
            int k0 = (c + 1) * 32;                                                 \
            uint32_t st_ = sb + ((c + 1) & 1) * STAGE_B;                           \
            size_t gA0 = (size_t)(m0 + lrow0) * CD + k0 + lc0 * 8;                 \
            size_t gA1 = (size_t)(m0 + lrow1) * CD + k0 + lc1 * 8;                 \
            size_t gB0 = (size_t)(n0 + lrow0) * CD + k0 + lc0 * 8;                 \
            size_t gB1 = (size_t)(n0 + lrow1) * CD + k0 + lc1 * 8;                 \
            uint32_t s0 = lrow0 * RSTRIDE + lc0 * 16;                              \
            uint32_t s1 = lrow1 * RSTRIDE + lc1 * 16;                              \
            cp16(st_ + 0 * TILE_B + s0, Ah_ + gA0);                                \
            cp16(st_ + 0 * TILE_B + s1, Ah_ + gA1);                                \
            cp16(st_ + 1 * TILE_B + s0, Al_ + gA0);                                \
            cp16(st_ + 1 * TILE_B + s1, Al_ + gA1);                                \
            cp16(st_ + 2 * TILE_B + s0, Bh_ + gB0);                                \
            cp16(st_ + 2 * TILE_B + s1, Bh_ + gB1);                                \
            cp16(st_ + 3 * TILE_B + s0, Bl_ + gB0);                                \
            cp16(st_ + 3 * TILE_B + s1, Bl_ + gB1);                                \
            CP_COMMIT();                                                           \
            asm volatile("cp.async.wait_group 1;" ::: "memory");                   \
        } else {                                                                   \
            asm volatile("cp.async.wait_group 0;" ::: "memory");                   \
        }                                                                          \
        __syncthreads();                                                           \
        const uint32_t st = sb + (c & 1) * STAGE_B;                                \
        _Pragma("unroll") for (int h = 0; h < 2; h++) {                            \
            uint32_t bh[8], bl[8];                                                 \
            _Pragma("unroll") for (int j2 = 0; j2 < 2; j2++) {                     \
                uint32_t off = (uint32_t)((wn + j2 * 16 + (lane & 15)) * RSTRIDE + \
                                          (h * 2 + (lane >> 4)) * 16);             \
                ldsm4(bh + j2 * 4, st + 2 * TILE_B + off);                         \
                ldsm4(bl + j2 * 4, st + 3 * TILE_B + off);                         \
            }                                                                      \
            _Pragma("unroll") for (int i = 0; i < 4; i++) {                        \
                uint32_t aoff = (uint32_t)((wm + i * 16 + (lane & 15)) * RSTRIDE + \
                                           (h * 2 + (lane >> 4)) * 16);            \
                uint32_t ah[4], al[4];                                             \
                ldsm4(ah, st + 0 * TILE_B + aoff);                                 \
                ldsm4(al, st + 1 * TILE_B + aoff);                                 \
                _Pragma("unroll") for (int j = 0; j < 4; j++) {                    \
                    uint32_t bh2[2] = {bh[(j >> 1) * 4 + (j & 1)],                 \
                                       bh[(j >> 1) * 4 + 2 + (j & 1)]};            \
                    uint32_t bl2[2] = {bl[(j >> 1) * 4 + (j & 1)],                 \
                                       bl[(j >> 1) * 4 + 2 + (j & 1)]};            \
                    mma16816(acc[i][j], ah, bh2);                                  \
                    mma16816(acc[i][j], ah, bl2);                                  \
                    mma16816(acc[i][j], al, bh2);                                  \
                }                                                                  \
            }                                                                      \
        }                                                                          \
        __syncthreads();                                                           \
    }

// ---- the 3 projection GEMMs in one launch ----------------------------------
__global__ __launch_bounds__(256, 2) void gemm3() {
    extern __shared__ __align__(128) char smem[];
    const uint32_t sb = smem_u32(smem);
    const int tid = threadIdx.x, wid = tid >> 5, lane = tid & 31;
    const int mode = (int)(blockIdx.x >> 3);          // 0=K 1=V 2=Sf
    const int n0 = (int)(blockIdx.x & 7) * 128;
    const int m0 = (int)blockIdx.y * 128;
    const int wm = (wid >> 2) * 64;
    const int wn = (wid & 3) * 32;

    const __nv_bfloat16* Bh = g_wh[mode];
    const __nv_bfloat16* Bl = g_wl[mode];

    GEMM_CORE(g_xh, g_xl, Bh, Bl)

    // ---- epilogue per mode --------------------------------------------------
#pragma unroll
    for (int i = 0; i < 4; i++) {
        const int m = m0 + wm + i * 16 + (lane >> 2);
#pragma unroll
        for (int j = 0; j < 4; j++) {
            const int n = n0 + wn + j * 8 + (lane & 3) * 2;
            const size_t o0 = (size_t)m * CD + n;
            const size_t o1 = (size_t)(m + 8) * CD + n;
            if (mode == 2) {
                *(float2*)(g_Sf + o0) = make_float2(acc[i][j][0], acc[i][j][1]);
                *(float2*)(g_Sf + o1) = make_float2(acc[i][j][2], acc[i][j][3]);
            } else if (mode == 0) {
                store_split2(g_Kh, g_Kl, o0, acc[i][j][0], acc[i][j][1]);
                store_split2(g_Kh, g_Kl, o1, acc[i][j][2], acc[i][j][3]);
            } else {
                *(__nv_bfloat162*)(g_Vb + o0) =
                    __floats2bfloat162_rn(acc[i][j][0], acc[i][j][1]);
                *(__nv_bfloat162*)(g_Vb + o1) =
                    __floats2bfloat162_rn(acc[i][j][2], acc[i][j][3]);
            }
        }
    }
}

// ---- final GEMM: (P+Sf) @ Wout^T -> out ------------------------------------
__global__ __launch_bounds__(256, 2) void gemm_out(float* __restrict__ Cout) {
    extern __shared__ __align__(128) char smem[];
    const uint32_t sb = smem_u32(smem);
    const int tid = threadIdx.x, wid = tid >> 5, lane = tid & 31;
    const int n0 = (int)blockIdx.x * 128;
    const int m0 = (int)blockIdx.y * 128;
    const int wm = (wid >> 2) * 64;
    const int wn = (wid & 3) * 32;

    const __nv_bfloat16* Bh = g_wh[3];
    const __nv_bfloat16* Bl = g_wl[3];

    GEMM_CORE(g_xh, g_xl, Bh, Bl)

#pragma unroll
    for (int i = 0; i < 4; i++) {
        const int m = m0 + wm + i * 16 + (lane >> 2);
#pragma unroll
        for (int j = 0; j < 4; j++) {
            const int n = n0 + wn + j * 8 + (lane & 3) * 2;
            *(float2*)(Cout + (size_t)m * CD + n) = make_float2(acc[i][j][0], acc[i][j][1]);
            *(float2*)(Cout + (size_t)(m + 8) * CD + n) = make_float2(acc[i][j][2], acc[i][j][3]);
        }
    }
}

// ============================================================================
// FA2-style causal attention on HMMA (Q == K), verified R5.
// Epilogue fused: P_norm + Sf -> split -> g_xh/g_xl (A operand of gemm_out).
// ============================================================================
constexpr int A_RS = 272;
constexpr int A_TILE = 64 * A_RS;
constexpr int A_SMEM = 5 * A_TILE;

__global__ __launch_bounds__(128, 2) void fattn() {
    extern __shared__ __align__(128) char smem[];
    const uint32_t sb = smem_u32(smem);
    const uint32_t SQH = 0, SQL = A_TILE, SKH = 2 * A_TILE, SKL = 3 * A_TILE, SVB = 4 * A_TILE;

    const int qb = (int)(gridDim.x - 1 - blockIdx.x);  // heaviest first
    const int bh = blockIdx.y;
    const int b = bh >> 3, h = bh & 7;
    const int q0 = qb * 64;

    const int tid = threadIdx.x, wid = tid >> 5, lane = tid & 31;

    const __nv_bfloat16* Khg = g_Kh + (size_t)b * CS * CD + h * CHD;
    const __nv_bfloat16* Klg = g_Kl + (size_t)b * CS * CD + h * CHD;
    const __nv_bfloat16* Vbg = g_Vb + (size_t)b * CS * CD + h * CHD;

    for (int t = tid; t < 64 * 16; t += 128) {
        int row = t >> 4, g = t & 15;
        uint32_t so = (uint32_t)(row * A_RS + g * 16);
        cp16(sb + SQH + so, Khg + (size_t)(q0 + row) * CD + g * 8);
        cp16(sb + SQL + so, Klg + (size_t)(q0 + row) * CD + g * 8);
    }
    CP_COMMIT();

    float o[16][4];
#pragma unroll
    for (int t = 0; t < 16; t++)
#pragma unroll
        for (int r = 0; r < 4; r++) o[t][r] = 0.f;
    float m0r = -1e30f, m1r = -1e30f, l0 = 0.f, l1 = 0.f;
    const float scale = 0.08838834764831845f;  // 1/sqrt(128)

    for (int kb = 0; kb <= qb; kb++) {
        const int k0 = kb * 64;
        __syncthreads();
        for (int t = tid; t < 64 * 16; t += 128) {
            int row = t >> 4, g = t & 15;
            uint32_t so = (uint32_t)(row * A_RS + g * 16);
            cp16(sb + SKH + so, Khg + (size_t)(k0 + row) * CD + g * 8);
            cp16(sb + SKL + so, Klg + (size_t)(k0 + row) * CD + g * 8);
            cp16(sb + SVB + so, Vbg + (size_t)(k0 + row) * CD + g * 8);
        }
        CP_COMMIT();
        asm volatile("cp.async.wait_group 0;" ::: "memory");
        __syncthreads();

        float s[8][4];
#pragma unroll
        for (int j = 0; j < 8; j++)
#pragma unroll
            for (int r = 0; r < 4; r++) s[j][r] = 0.f;

#pragma unroll
        for (int ks = 0; ks < 8; ks++) {
            uint32_t qoff = (uint32_t)((wid * 16 + (lane & 15)) * A_RS + ks * 32 +
                                       (lane >> 4) * 16);
            uint32_t qh[4], ql[4];
            ldsm4(qh, sb + SQH + qoff);
            ldsm4(ql, sb + SQL + qoff);
            uint32_t khf[16], klf[16];
#pragma unroll
            for (int j4 = 0; j4 < 4; j4++) {
                uint32_t koff = (uint32_t)((j4 * 16 + (lane & 15)) * A_RS + ks * 32 +
                                           (lane >> 4) * 16);
                ldsm4(khf + j4 * 4, sb + SKH + koff);
                ldsm4(klf + j4 * 4, sb + SKL + koff);
            }
#pragma unroll
            for (int j = 0; j < 8; j++) {
                uint32_t bh2[2] = {khf[(j >> 1) * 4 + (j & 1)], khf[(j >> 1) * 4 + 2 + (j & 1)]};
                uint32_t bl2[2] = {klf[(j >> 1) * 4 + (j & 1)], klf[(j >> 1) * 4 + 2 + (j & 1)]};
                mma16816(s[j], qh, bh2);
                mma16816(s[j], qh, bl2);
                mma16816(s[j], ql, bh2);
            }
        }

        const int r0l = wid * 16 + (lane >> 2);
#pragma unroll
        for (int j = 0; j < 8; j++) {
#pragma unroll
            for (int r = 0; r < 4; r++) s[j][r] = -s[j][r] * scale;
            if (kb == qb) {
                int cl = j * 8 + (lane & 3) * 2;
                if (cl > r0l) s[j][0] = -1e30f;
                if (cl + 1 > r0l) s[j][1] = -1e30f;
                if (cl > r0l + 8) s[j][2] = -1e30f;
                if (cl + 1 > r0l + 8) s[j][3] = -1e30f;
            }
        }

        float mx0 = -1e30f, mx1 = -1e30f;
#pragma unroll
        for (int j = 0; j < 8; j++) {
            mx0 = fmaxf(mx0, fmaxf(s[j][0], s[j][1]));
            mx1 = fmaxf(mx1, fmaxf(s[j][2], s[j][3]));
        }
        mx0 = fmaxf(mx0, __shfl_xor_sync(0xffffffffu, mx0, 1));
        mx0 = fmaxf(mx0, __shfl_xor_sync(0xffffffffu, mx0, 2));
        mx1 = fmaxf(mx1, __shfl_xor_sync(0xffffffffu, mx1, 1));
        mx1 = fmaxf(mx1, __shfl_xor_sync(0xffffffffu, mx1, 2));
        const float mn0 = fmaxf(m0r, mx0), mn1 = fmaxf(m1r, mx1);
        const float a0 = __expf(m0r - mn0), a1 = __expf(m1r - mn1);
        float sum0 = 0.f, sum1 = 0.f;
#pragma unroll
        for (int j = 0; j < 8; j++) {
            s[j][0] = __expf(s[j][0] - mn0);
            s[j][1] = __expf(s[j][1] - mn0);
            s[j][2] = __expf(s[j][2] - mn1);
            s[j][3] = __expf(s[j][3] - mn1);
            sum0 += s[j][0] + s[j][1];
            sum1 += s[j][2] + s[j][3];
        }
        sum0 += __shfl_xor_sync(0xffffffffu, sum0, 1);
        sum0 += __shfl_xor_sync(0xffffffffu, sum0, 2);
        sum1 += __shfl_xor_sync(0xffffffffu, sum1, 1);
        sum1 += __shfl_xor_sync(0xffffffffu, sum1, 2);
        l0 = l0 * a0 + sum0;
        l1 = l1 * a1 + sum1;
        m0r = mn0; m1r = mn1;
#pragma unroll
        for (int t = 0; t < 16; t++) {
            o[t][0] *= a0; o[t][1] *= a0; o[t][2] *= a1; o[t][3] *= a1;
        }

#pragma unroll
        for (int kg = 0; kg < 4; kg++) {
            uint32_t pa[4];
            {
                __nv_bfloat162 t0 = __floats2bfloat162_rn(s[2 * kg][0], s[2 * kg][1]);
                __nv_bfloat162 t1 = __floats2bfloat162_rn(s[2 * kg][2], s[2 * kg][3]);
                __nv_bfloat162 t2 = __floats2bfloat162_rn(s[2 * kg + 1][0], s[2 * kg + 1][1]);
                __nv_bfloat162 t3 = __floats2bfloat162_rn(s[2 * kg + 1][2], s[2 * kg + 1][3]);
                pa[0] = *(uint32_t*)&t0; pa[1] = *(uint32_t*)&t1;
                pa[2] = *(uint32_t*)&t2; pa[3] = *(uint32_t*)&t3;
            }
#pragma unroll
            for (int n2 = 0; n2 < 8; n2++) {
                uint32_t voff = (uint32_t)((kg * 16 + (lane & 15)) * A_RS + n2 * 32 +
                                           (lane >> 4) * 16);
                uint32_t vf[4];
                ldsm4t(vf, sb + SVB + voff);
                uint32_t b0[2] = {vf[0], vf[1]};
                uint32_t b1[2] = {vf[2], vf[3]};
                mma16816(o[2 * n2], pa, b0);
                mma16816(o[2 * n2 + 1], pa, b1);
            }
        }
    }

    // ---- fused epilogue: (P_norm + Sf) -> split -> g_xh/g_xl ----------------
    const float inv0 = 1.f / l0, inv1 = 1.f / l1;
    const size_t row0 = (size_t)(b * CS + q0 + wid * 16 + (lane >> 2));
#pragma unroll
    for (int t = 0; t < 16; t++) {
        const int col = h * CHD + t * 8 + (lane & 3) * 2;
        const size_t o0 = row0 * CD + col;
        const size_t o1 = (row0 + 8) * CD + col;
        float2 sf0 = *(const float2*)(g_Sf + o0);
        float2 sf1 = *(const float2*)(g_Sf + o1);
        store_split2(g_xh, g_xl, o0, o[t][0] * inv0 + sf0.x, o[t][1] * inv0 + sf0.y);
        store_split2(g_xh, g_xl, o1, o[t][2] * inv1 + sf1.x, o[t][3] * inv1 + sf1.y);
    }
}

// ============================================================================
// launch
// ============================================================================
extern "C" void kernel_launch(void* const* d_in, const int* in_sizes, int n_in,
                              void* d_out, int out_size) {
    const float* x  = (const float*)d_in[0];
    const float* Wk = (const float*)d_in[1];
    const float* Wv = (const float*)d_in[2];
    const float* Ws = (const float*)d_in[3];
    const float* Wo = (const float*)d_in[4];
    float* out = (float*)d_out;

    cudaFuncSetAttribute(gemm3, cudaFuncAttributeMaxDynamicSharedMemorySize, G_SMEM);
    cudaFuncSetAttribute(gemm_out, cudaFuncAttributeMaxDynamicSharedMemorySize, G_SMEM);
    cudaFuncSetAttribute(fattn, cudaFuncAttributeMaxDynamicSharedMemorySize, A_SMEM);

    const int PB = (int)((XQ + 4 * WQ) / 256);        // 8192 blocks
    prep<<<PB, 256>>>(x, Wk, Wv, Ws, Wo);

    gemm3<<<dim3(24, CM / 128), 256, G_SMEM>>>();     // -> g_Kh/g_Kl, g_Vb, g_Sf

    fattn<<<dim3(CS / 64, CB * CH), 128, A_SMEM>>>(); // -> g_xh/g_xl (=P+Sf split)

    gemm_out<<<dim3(CD / 128, CM / 128), 256, G_SMEM>>>(out);
}